// round 17
// baseline (speedup 1.0000x reference)
#include <cuda_runtime.h>
#include <cuda_bf16.h>
#include <stdint.h>
#include <math.h>

#define Bb 8
#define Cc 512
#define Ll 2048
#define CQq 128

// Static device scratch (allocation-free rule: __device__ globals).
__device__ __nv_bfloat16 g_qhi[(size_t)Bb * Ll * CQq];   // [b][pos][d]
__device__ __nv_bfloat16 g_qlo[(size_t)Bb * Ll * CQq];
__device__ __nv_bfloat16 g_khi[(size_t)Bb * Ll * CQq];
__device__ __nv_bfloat16 g_klo[(size_t)Bb * Ll * CQq];
__device__ float g_v[(size_t)Bb * Cc * Ll];              // gamma!=0 path only
__device__ float g_att[(size_t)Bb * Ll * Ll];            // fallback
__device__ float g_outbuf[(size_t)Bb * Cc * Ll];         // fallback

// 64-wide K chunks in smem, pitch 72 -> ldmatrix 8-row x 16B reads cover all
// 32 banks exactly once (conflict-free).
#define CPAD 72
#define T64 (128 * CPAD)              // 9216 bf16 per tile
#define MMA_SMEM_B (4 * T64 * 2)      // 73728 bytes (Ahi,Alo,Bhi,Blo)

// ---------------------------------------------------------------------------
// mma / ldmatrix helpers
// ---------------------------------------------------------------------------
__device__ __forceinline__ void mma16816(float* acc, const uint32_t* a,
                                         const uint32_t* bfr)
{
    asm volatile(
        "mma.sync.aligned.m16n8k16.row.col.f32.bf16.bf16.f32 "
        "{%0,%1,%2,%3}, {%4,%5,%6,%7}, {%8,%9}, {%0,%1,%2,%3};\n"
        : "+f"(acc[0]), "+f"(acc[1]), "+f"(acc[2]), "+f"(acc[3])
        : "r"(a[0]), "r"(a[1]), "r"(a[2]), "r"(a[3]),
          "r"(bfr[0]), "r"(bfr[1]));
}

__device__ __forceinline__ void ldsm_x4(uint32_t* r, uint32_t addr)
{
    asm volatile(
        "ldmatrix.sync.aligned.m8n8.x4.shared.b16 {%0,%1,%2,%3}, [%4];\n"
        : "=r"(r[0]), "=r"(r[1]), "=r"(r[2]), "=r"(r[3]) : "r"(addr));
}

// per-lane ldmatrix offsets (bf16-element units, relative to tile base)
__device__ __forceinline__ uint32_t a_frag_off72(int wm, int lane)
{
    return (uint32_t)((wm * 64 + (lane & 15)) * CPAD + ((lane >> 4) << 3));
}
__device__ __forceinline__ uint32_t b_frag_off72(int wn, int lane)
{
    return (uint32_t)((wn * 32 + ((lane >> 4) << 3) + (lane & 7)) * CPAD
                      + (((lane >> 3) & 1) << 3));
}

// ---------------------------------------------------------------------------
// Compute one 64-wide chunk: 4 k-steps, 3-combo split bf16, ldmatrix frags.
// ---------------------------------------------------------------------------
__device__ __forceinline__ void kchunk64_mma(
    uint32_t smU, uint32_t a_off, uint32_t b_off, float acc[4][4][4])
{
    const uint32_t AhiU = smU;
    const uint32_t AloU = smU + T64 * 2;
    const uint32_t BhiU = smU + 2 * T64 * 2;
    const uint32_t BloU = smU + 3 * T64 * 2;
    #pragma unroll
    for (int ks = 0; ks < 4; ks++) {
        const int k0 = ks * 16;
        uint32_t bh[2][4], bl[2][4];
        #pragma unroll
        for (int p = 0; p < 2; p++) {
            const uint32_t bo = 2u * (b_off + (uint32_t)(p * 16 * CPAD + k0));
            ldsm_x4(bh[p], BhiU + bo);
            ldsm_x4(bl[p], BloU + bo);
        }
        #pragma unroll
        for (int am = 0; am < 4; am++) {
            const uint32_t ao = 2u * (a_off + (uint32_t)(am * 16 * CPAD + k0));
            uint32_t ah[4], al[4];
            ldsm_x4(ah, AhiU + ao);
            ldsm_x4(al, AloU + ao);
            #pragma unroll
            for (int bn = 0; bn < 4; bn++) {
                const uint32_t* bhp = &bh[bn >> 1][(bn & 1) * 2];
                const uint32_t* blp = &bl[bn >> 1][(bn & 1) * 2];
                mma16816(acc[am][bn], ah, bhp);
                mma16816(acc[am][bn], ah, blp);
                mma16816(acc[am][bn], al, bhp);
            }
        }
    }
}

// ---------------------------------------------------------------------------
// FUSED q/k conv: reads fp32 x (transposing + splitting inline) and fp32 W
// (splitting inline). Also writes out = x on the s==0 pass when gamma==0.
// out[pos][d] = sum_c x[c][pos] * W[d][c] + bias[d]  -> split bf16 [pos][d].
// grid (L/128, 2 {q,k}, B), block 256 (8 warps, 2m x 4n), K=512 in 8 chunks.
// ---------------------------------------------------------------------------
__global__ __launch_bounds__(256, 2)
void qkconv_fused_kernel(const float* __restrict__ x,
                         const float* __restrict__ q_w, const float* __restrict__ q_b,
                         const float* __restrict__ k_w, const float* __restrict__ k_b,
                         float* __restrict__ out, const float* __restrict__ gamma)
{
    extern __shared__ __nv_bfloat16 sm[];
    __nv_bfloat16* Ahi = sm;
    __nv_bfloat16* Alo = sm + T64;
    __nv_bfloat16* Bhi = sm + 2 * T64;
    __nv_bfloat16* Blo = sm + 3 * T64;
    __shared__ float sbias[128];

    const int p0 = blockIdx.x * 128;
    const int s  = blockIdx.y;
    const int b  = blockIdx.z;

    const float* W    = s ? k_w : q_w;
    const float* bias = s ? k_b : q_b;
    const bool docopy = (s == 0) && (gamma[0] == 0.0f);

    const int tid  = threadIdx.x;
    const int lane = tid & 31;
    const int wid  = tid >> 5;
    const int wm   = wid >> 2;
    const int wn   = wid & 3;
    const int g    = lane >> 2;
    const int t    = lane & 3;

    if (tid < 128) sbias[tid] = bias[tid];

    const uint32_t smU = (uint32_t)__cvta_generic_to_shared(sm);
    const uint32_t a_off = a_frag_off72(wm, lane);
    const uint32_t b_off = b_frag_off72(wn, lane);

    const float* xb = x + (size_t)b * Cc * Ll;
    float* ob = out + (size_t)b * Cc * Ll;

    float acc[4][4][4];
    #pragma unroll
    for (int am = 0; am < 4; am++)
        #pragma unroll
        for (int bn = 0; bn < 4; bn++)
            #pragma unroll
            for (int c = 0; c < 4; c++) acc[am][bn][c] = 0.0f;

    for (int it = 0; it < 8; it++) {
        const int c0 = it * 64;
        if (it) __syncthreads();

        // x tile: 64 c-rows x 128 pos, coalesced float4 along l.
        // Split + transposed store into Ahi/Alo [pos][c].
        #pragma unroll
        for (int q = 0; q < 8; q++) {
            const int id = q * 256 + tid;
            const int c  = id >> 5;          // 0..63
            const int p4 = (id & 31) * 4;    // 0..124
            const size_t goff = (size_t)(c0 + c) * Ll + p0 + p4;
            float4 v = *(const float4*)&xb[goff];
            if (docopy) *(float4*)&ob[goff] = v;
            float vv[4] = {v.x, v.y, v.z, v.w};
            #pragma unroll
            for (int j = 0; j < 4; j++) {
                __nv_bfloat16 h = __float2bfloat16_rn(vv[j]);
                Ahi[(p4 + j) * CPAD + c] = h;
                Alo[(p4 + j) * CPAD + c] =
                    __float2bfloat16_rn(vv[j] - __bfloat162float(h));
            }
        }
        // W tile: 128 d-rows x 64 c, coalesced float4 along c.
        #pragma unroll
        for (int q = 0; q < 8; q++) {
            const int id = q * 256 + tid;
            const int d  = id >> 4;          // 0..127
            const int cc = (id & 15) * 4;    // 0..60
            float4 v = *(const float4*)&W[(size_t)d * Cc + c0 + cc];
            float vv[4] = {v.x, v.y, v.z, v.w};
            __nv_bfloat16 h[4], l[4];
            #pragma unroll
            for (int j = 0; j < 4; j++) {
                h[j] = __float2bfloat16_rn(vv[j]);
                l[j] = __float2bfloat16_rn(vv[j] - __bfloat162float(h[j]));
            }
            *(uint2*)&Bhi[d * CPAD + cc] = *(uint2*)h;
            *(uint2*)&Blo[d * CPAD + cc] = *(uint2*)l;
        }
        __syncthreads();
        kchunk64_mma(smU, a_off, b_off, acc);
    }

    __nv_bfloat16* hb = (s ? g_khi : g_qhi) + (size_t)b * Ll * CQq;
    __nv_bfloat16* lb = (s ? g_klo : g_qlo) + (size_t)b * Ll * CQq;
    #pragma unroll
    for (int am = 0; am < 4; am++) {
        const int r0 = wm * 64 + am * 16 + g;
        #pragma unroll
        for (int bn = 0; bn < 4; bn++) {
            const int col = wn * 32 + bn * 8 + 2 * t;
            const float b0 = sbias[col], b1 = sbias[col + 1];
            #pragma unroll
            for (int half = 0; half < 2; half++) {
                const int row = r0 + half * 8;
                const float v0 = acc[am][bn][half * 2 + 0] + b0;
                const float v1 = acc[am][bn][half * 2 + 1] + b1;
                __nv_bfloat16 h0 = __float2bfloat16_rn(v0);
                __nv_bfloat16 h1 = __float2bfloat16_rn(v1);
                __nv_bfloat16 l0 = __float2bfloat16_rn(v0 - __bfloat162float(h0));
                __nv_bfloat16 l1 = __float2bfloat16_rn(v1 - __bfloat162float(h1));
                *(__nv_bfloat162*)&hb[(size_t)(p0 + row) * CQq + col] =
                    __halves2bfloat162(h0, h1);
                *(__nv_bfloat162*)&lb[(size_t)(p0 + row) * CQq + col] =
                    __halves2bfloat162(l0, l1);
            }
        }
    }
}

// ---------------------------------------------------------------------------
// energy: 64-wide chunks, LDG+STS, CPAD=72 tiles (best measured form).
// ---------------------------------------------------------------------------
__global__ __launch_bounds__(256, 2)
void energy_mma_kernel(float* __restrict__ E)
{
    extern __shared__ __nv_bfloat16 sm[];
    __nv_bfloat16* Ahi = sm;
    __nv_bfloat16* Alo = sm + T64;
    __nv_bfloat16* Bhi = sm + 2 * T64;
    __nv_bfloat16* Blo = sm + 3 * T64;

    const int b  = blockIdx.z;
    const int i0 = blockIdx.y * 128;
    const int j0 = blockIdx.x * 128;

    const int tid  = threadIdx.x;
    const int lane = tid & 31;
    const int wid  = tid >> 5;
    const int wm   = wid >> 2;
    const int wn   = wid & 3;
    const int g    = lane >> 2;
    const int t    = lane & 3;

    const uint32_t smU = (uint32_t)__cvta_generic_to_shared(sm);
    const uint32_t a_off = a_frag_off72(wm, lane);
    const uint32_t b_off = b_frag_off72(wn, lane);

    const size_t boff = (size_t)b * Ll * CQq;
    const __nv_bfloat16* qh = g_qhi + boff;
    const __nv_bfloat16* ql = g_qlo + boff;
    const __nv_bfloat16* kh = g_khi + boff;
    const __nv_bfloat16* kl = g_klo + boff;

    float acc[4][4][4];
    #pragma unroll
    for (int am = 0; am < 4; am++)
        #pragma unroll
        for (int bn = 0; bn < 4; bn++)
            #pragma unroll
            for (int c = 0; c < 4; c++) acc[am][bn][c] = 0.0f;

    #pragma unroll
    for (int it = 0; it < 2; it++) {
        const int c0 = it * 64;
        if (it) __syncthreads();
        #pragma unroll
        for (int q = 0; q < 4; q++) {
            const int idx = q * 256 + tid;
            const int r  = idx >> 3;
            const int cc = (idx & 7) * 8;
            *(uint4*)&Ahi[r * CPAD + cc] = *(const uint4*)&qh[(size_t)(i0 + r) * CQq + c0 + cc];
            *(uint4*)&Alo[r * CPAD + cc] = *(const uint4*)&ql[(size_t)(i0 + r) * CQq + c0 + cc];
            *(uint4*)&Bhi[r * CPAD + cc] = *(const uint4*)&kh[(size_t)(j0 + r) * CQq + c0 + cc];
            *(uint4*)&Blo[r * CPAD + cc] = *(const uint4*)&kl[(size_t)(j0 + r) * CQq + c0 + cc];
        }
        __syncthreads();
        kchunk64_mma(smU, a_off, b_off, acc);
    }

    float* eb = E + (size_t)b * Ll * Ll;
    #pragma unroll
    for (int am = 0; am < 4; am++) {
        const int row = i0 + wm * 64 + am * 16 + g;
        #pragma unroll
        for (int bn = 0; bn < 4; bn++) {
            const int col = j0 + wn * 32 + bn * 8 + 2 * t;
            *(float2*)&eb[(size_t)row * Ll + col] =
                make_float2(acc[am][bn][0], acc[am][bn][1]);
            *(float2*)&eb[(size_t)(row + 8) * Ll + col] =
                make_float2(acc[am][bn][2], acc[am][bn][3]);
        }
    }
}

// ---------------------------------------------------------------------------
// In-place row softmax, WARP-PER-ROW: 64 floats/lane in registers, pure
// shuffle reductions, zero block barriers. grid = B*L/8, block 256.
// ---------------------------------------------------------------------------
__global__ __launch_bounds__(256)
void softmax_kernel(float* __restrict__ att)
{
    const int lane = threadIdx.x & 31;
    const int wid  = threadIdx.x >> 5;
    const size_t row = (size_t)blockIdx.x * 8 + wid;
    float4* p = (float4*)(att + row * (size_t)Ll);

    float4 v[16];
    float m = -INFINITY;
    #pragma unroll
    for (int i = 0; i < 16; i++) {
        v[i] = p[lane + 32 * i];
        m = fmaxf(m, fmaxf(fmaxf(v[i].x, v[i].y), fmaxf(v[i].z, v[i].w)));
    }
    #pragma unroll
    for (int s = 16; s > 0; s >>= 1)
        m = fmaxf(m, __shfl_xor_sync(0xffffffffu, m, s));

    float sum = 0.0f;
    #pragma unroll
    for (int i = 0; i < 16; i++) {
        v[i].x = __expf(v[i].x - m);
        v[i].y = __expf(v[i].y - m);
        v[i].z = __expf(v[i].z - m);
        v[i].w = __expf(v[i].w - m);
        sum += (v[i].x + v[i].y) + (v[i].z + v[i].w);
    }
    #pragma unroll
    for (int s = 16; s > 0; s >>= 1)
        sum += __shfl_xor_sync(0xffffffffu, sum, s);
    const float inv = 1.0f / sum;

    #pragma unroll
    for (int i = 0; i < 16; i++) {
        v[i].x *= inv; v[i].y *= inv; v[i].z *= inv; v[i].w *= inv;
        p[lane + 32 * i] = v[i];
    }
}

// ---------------------------------------------------------------------------
// gamma != 0 path kernels (gated; full-precision fallback).
// ---------------------------------------------------------------------------
__global__ __launch_bounds__(256)
void vconv_kernel(const float* __restrict__ W, const float* __restrict__ bias,
                  const float* __restrict__ x, float* __restrict__ out,
                  const float* __restrict__ gamma)
{
    if (gamma[0] == 0.0f) return;
    const int b  = blockIdx.z;
    const int m0 = blockIdx.y * 128;
    const int n0 = blockIdx.x * 128;

    __shared__ float As[8][128];
    __shared__ float Bs[8][128];

    const int tid = threadIdx.x;
    const int tx = tid % 16, ty = tid / 16;
    const float* xb = x + (size_t)b * Cc * Ll;

    const int aRow = tid >> 1;
    const int aCol = (tid & 1) * 4;
    const int bRow = tid >> 5;
    const int bCol = (tid & 31) * 4;

    float acc[8][8];
    #pragma unroll
    for (int i = 0; i < 8; i++)
        #pragma unroll
        for (int j = 0; j < 8; j++) acc[i][j] = 0.0f;

    for (int k0 = 0; k0 < Cc; k0 += 8) {
        float4 a = *(const float4*)&W[(size_t)(m0 + aRow) * Cc + k0 + aCol];
        As[aCol + 0][aRow] = a.x;
        As[aCol + 1][aRow] = a.y;
        As[aCol + 2][aRow] = a.z;
        As[aCol + 3][aRow] = a.w;
        *(float4*)&Bs[bRow][bCol] =
            *(const float4*)&xb[(size_t)(k0 + bRow) * Ll + n0 + bCol];
        __syncthreads();

        #pragma unroll
        for (int k = 0; k < 8; k++) {
            float rm[8], rn[8];
            #pragma unroll
            for (int i = 0; i < 8; i++) rm[i] = As[k][ty * 8 + i];
            #pragma unroll
            for (int j = 0; j < 8; j++) rn[j] = Bs[k][tx * 8 + j];
            #pragma unroll
            for (int i = 0; i < 8; i++)
                #pragma unroll
                for (int j = 0; j < 8; j++)
                    acc[i][j] = fmaf(rm[i], rn[j], acc[i][j]);
        }
        __syncthreads();
    }

    float* ob = out + (size_t)b * Cc * Ll;
    #pragma unroll
    for (int i = 0; i < 8; i++) {
        const int m = m0 + ty * 8 + i;
        const float bb = bias[m];
        float* po = ob + (size_t)m * Ll + n0 + tx * 8;
        *(float4*)po = make_float4(acc[i][0] + bb, acc[i][1] + bb,
                                   acc[i][2] + bb, acc[i][3] + bb);
        *(float4*)(po + 4) = make_float4(acc[i][4] + bb, acc[i][5] + bb,
                                         acc[i][6] + bb, acc[i][7] + bb);
    }
}

__global__ __launch_bounds__(256)
void outgemm_kernel(const float* __restrict__ att, const float* __restrict__ x,
                    float* __restrict__ out, const float* __restrict__ gamma)
{
    const float g = gamma[0];
    if (g == 0.0f) return;
    const int b  = blockIdx.z;
    const int c0 = blockIdx.y * 128;
    const int i0 = blockIdx.x * 128;

    __shared__ float Vs[8][128];
    __shared__ float Ts[8][128];

    const int tid = threadIdx.x;
    const int tx = tid % 16, ty = tid / 16;
    const int aRow = tid >> 1;
    const int aCol = (tid & 1) * 4;

    const float* vb = g_v + (size_t)b * Cc * Ll;
    const float* ab = att + (size_t)b * Ll * Ll;

    float acc[8][8];
    #pragma unroll
    for (int i = 0; i < 8; i++)
        #pragma unroll
        for (int j = 0; j < 8; j++) acc[i][j] = 0.0f;

    for (int j0 = 0; j0 < Ll; j0 += 8) {
        float4 a = *(const float4*)&vb[(size_t)(c0 + aRow) * Ll + j0 + aCol];
        Vs[aCol + 0][aRow] = a.x;
        Vs[aCol + 1][aRow] = a.y;
        Vs[aCol + 2][aRow] = a.z;
        Vs[aCol + 3][aRow] = a.w;
        float4 tt = *(const float4*)&ab[(size_t)(i0 + aRow) * Ll + j0 + aCol];
        Ts[aCol + 0][aRow] = tt.x;
        Ts[aCol + 1][aRow] = tt.y;
        Ts[aCol + 2][aRow] = tt.z;
        Ts[aCol + 3][aRow] = tt.w;
        __syncthreads();

        #pragma unroll
        for (int k = 0; k < 8; k++) {
            float rm[8], rn[8];
            #pragma unroll
            for (int i = 0; i < 8; i++) rm[i] = Vs[k][ty * 8 + i];
            #pragma unroll
            for (int j = 0; j < 8; j++) rn[j] = Ts[k][tx * 8 + j];
            #pragma unroll
            for (int i = 0; i < 8; i++)
                #pragma unroll
                for (int j = 0; j < 8; j++)
                    acc[i][j] = fmaf(rm[i], rn[j], acc[i][j]);
        }
        __syncthreads();
    }

    #pragma unroll
    for (int i = 0; i < 8; i++) {
        const size_t off = (size_t)b * Cc * Ll + (size_t)(c0 + ty * 8 + i) * Ll
                         + i0 + tx * 8;
        #pragma unroll
        for (int j = 0; j < 8; j++)
            out[off + j] = g * acc[i][j] + x[off + j];
    }
}

// ---------------------------------------------------------------------------
extern "C" void kernel_launch(void* const* d_in, const int* in_sizes, int n_in,
                              void* d_out, int out_size)
{
    (void)in_sizes; (void)n_in;
    const float* x     = (const float*)d_in[0];
    const float* q_w   = (const float*)d_in[1];
    const float* q_b   = (const float*)d_in[2];
    const float* k_w   = (const float*)d_in[3];
    const float* k_b   = (const float*)d_in[4];
    const float* v_w   = (const float*)d_in[5];
    const float* v_b   = (const float*)d_in[6];
    const float* gamma = (const float*)d_in[7];

    const size_t BCL = (size_t)Bb * Cc * Ll;        // 8388608
    const size_t BLL = (size_t)Bb * Ll * Ll;        // 33554432

    float* out_ptr;
    float* att_ptr;
    if ((size_t)out_size >= BCL + BLL) {
        out_ptr = (float*)d_out;
        att_ptr = (float*)d_out + BCL;
    } else if ((size_t)out_size == BLL) {
        cudaGetSymbolAddress((void**)&out_ptr, g_outbuf);
        att_ptr = (float*)d_out;
    } else {
        out_ptr = (float*)d_out;
        cudaGetSymbolAddress((void**)&att_ptr, g_att);
    }
    float* vbuf; cudaGetSymbolAddress((void**)&vbuf, g_v);

    static int smem_set = 0;
    if (!smem_set) {
        cudaFuncSetAttribute(energy_mma_kernel,
                             cudaFuncAttributeMaxDynamicSharedMemorySize,
                             MMA_SMEM_B);
        cudaFuncSetAttribute(qkconv_fused_kernel,
                             cudaFuncAttributeMaxDynamicSharedMemorySize,
                             MMA_SMEM_B);
        smem_set = 1;
    }

    dim3 blk(256);

    // fused q/k projections: read fp32 x directly (split+transpose inline),
    // also write out = x on the s==0 pass when gamma==0.
    qkconv_fused_kernel<<<dim3(Ll / 128, 2, Bb), blk, MMA_SMEM_B>>>(
        x, q_w, q_b, k_w, k_b, out_ptr, gamma);

    // energy on tensor cores -> attention region, softmax in place
    energy_mma_kernel<<<dim3(Ll / 128, Ll / 128, Bb), blk, MMA_SMEM_B>>>(att_ptr);
    softmax_kernel<<<dim3(Bb * Ll / 8), blk>>>(att_ptr);

    // gamma != 0 fallback path (no-ops when gamma == 0)
    vconv_kernel<<<dim3(Ll / 128, Cc / 128, Bb), blk>>>(v_w, v_b, x, vbuf, gamma);
    outgemm_kernel<<<dim3(Ll / 128, Cc / 128, Bb), blk>>>(att_ptr, x, out_ptr, gamma);
}